// round 1
// baseline (speedup 1.0000x reference)
#include <cuda_runtime.h>
#include <math.h>

#define NN      50000
#define IN_F    256
#define HID     128
#define HEADS   4
#define EE      800000
#define COLS    (HEADS * HID)          // 512
#define ALPHA_L 0.2f
#define INV_SCALE 0.04419417382415922f // 1/sqrt(512)
#define LN_EPS  1e-6f

// ---------------- scratch (static device memory; no allocations) ------------
__device__ float  g_X[(size_t)NN * COLS];   // 102.4 MB: per-head projected features
__device__ float  g_s1[NN * HEADS];
__device__ float  g_s2[NN * HEADS];
__device__ float4 g_es[EE];                 // per-edge scores (4 heads), CSR order
__device__ int    g_dsts[EE];               // dst per edge, CSR order
__device__ int    g_deg[NN];
__device__ int    g_rowptr[NN + 1];
__device__ int    g_cursor[NN];
__device__ int    g_is64;                   // edge dtype flag

// ---------------- helpers ---------------------------------------------------
__device__ __forceinline__ int load_edge(const void* e, long long idx) {
    if (g_is64) return (int)((const long long*)e)[idx];
    return ((const int*)e)[idx];
}

// ---------------- kernels ---------------------------------------------------
__global__ void zero_deg_kernel() {
    int i = blockIdx.x * blockDim.x + threadIdx.x;
    if (i < NN) g_deg[i] = 0;
}

// Detect int64 vs int32 edge buffer: for int64 (values < 2^31, nonneg) every
// odd 32-bit word is zero; for int32 those words are random node ids.
__global__ void detect_kernel(const int* edge_raw) {
    if (threadIdx.x == 0 && blockIdx.x == 0) {
        int z = 1;
        for (int i = 1; i < 4096; i += 2)
            if (edge_raw[i] != 0) { z = 0; break; }
        g_is64 = z;
    }
}

// Tiled fp32 GEMM: X[n, h*128+c] = sum_k emb[n,k] * W[h,c,k] + b[h,c]
// BM=BN=128, BK=16, 256 threads, 8x8 micro-tile. blockIdx.y = head.
__global__ __launch_bounds__(256) void gemm_kernel(
    const float* __restrict__ emb, const float* __restrict__ W,
    const float* __restrict__ bias)
{
    __shared__ float As[16][128];
    __shared__ float Bs[16][128];
    const int h   = blockIdx.y;
    const int bm  = blockIdx.x * 128;
    const int tid = threadIdx.x;
    const int tx  = tid & 15, ty = tid >> 4;
    const float* Wh = W + (size_t)h * HID * IN_F;

    float acc[8][8];
#pragma unroll
    for (int i = 0; i < 8; i++)
#pragma unroll
        for (int j = 0; j < 8; j++) acc[i][j] = 0.f;

    for (int k0 = 0; k0 < IN_F; k0 += 16) {
        // A tile: 128 rows x 16 k  (512 float4, 2 per thread), row 0 => zeros
#pragma unroll
        for (int l = 0; l < 2; l++) {
            int idx = tid * 2 + l;            // 0..511
            int row = idx >> 2;
            int c4  = (idx & 3) * 4;
            int grow = bm + row;
            float4 v = make_float4(0.f, 0.f, 0.f, 0.f);
            if (grow < NN && grow != 0)
                v = *reinterpret_cast<const float4*>(emb + (size_t)grow * IN_F + k0 + c4);
            As[c4 + 0][row] = v.x; As[c4 + 1][row] = v.y;
            As[c4 + 2][row] = v.z; As[c4 + 3][row] = v.w;
        }
        // B tile: 128 cols x 16 k from W[h][col][k]
#pragma unroll
        for (int l = 0; l < 2; l++) {
            int idx = tid * 2 + l;
            int col = idx >> 2;
            int c4  = (idx & 3) * 4;
            float4 v = *reinterpret_cast<const float4*>(Wh + (size_t)col * IN_F + k0 + c4);
            Bs[c4 + 0][col] = v.x; Bs[c4 + 1][col] = v.y;
            Bs[c4 + 2][col] = v.z; Bs[c4 + 3][col] = v.w;
        }
        __syncthreads();
#pragma unroll
        for (int kk = 0; kk < 16; kk++) {
            float a[8], b[8];
            *(float4*)&a[0] = *(const float4*)&As[kk][ty * 8];
            *(float4*)&a[4] = *(const float4*)&As[kk][ty * 8 + 4];
            *(float4*)&b[0] = *(const float4*)&Bs[kk][tx * 8];
            *(float4*)&b[4] = *(const float4*)&Bs[kk][tx * 8 + 4];
#pragma unroll
            for (int i = 0; i < 8; i++)
#pragma unroll
                for (int j = 0; j < 8; j++)
                    acc[i][j] = fmaf(a[i], b[j], acc[i][j]);
        }
        __syncthreads();
    }
#pragma unroll
    for (int i = 0; i < 8; i++) {
        int grow = bm + ty * 8 + i;
        if (grow >= NN) continue;
        float* orow = g_X + (size_t)grow * COLS + h * HID + tx * 8;
#pragma unroll
        for (int j = 0; j < 8; j++)
            orow[j] = acc[i][j] + bias[h * HID + tx * 8 + j];
    }
}

// s1[n,h] = X[n, h*128:...] . a[h,:128];  s2 with a[h,128:256]. Warp per (n,h).
__global__ __launch_bounds__(256) void s_kernel(const float* __restrict__ a_attn) {
    int w    = (blockIdx.x * blockDim.x + threadIdx.x) >> 5;
    int lane = threadIdx.x & 31;
    if (w >= NN * HEADS) return;
    int n = w >> 2, h = w & 3;
    const float* xr = g_X + (size_t)n * COLS + h * HID;
    const float* a1 = a_attn + h * 2 * HID;
    const float* a2 = a1 + HID;
    float p1 = 0.f, p2 = 0.f;
#pragma unroll
    for (int j = lane; j < HID; j += 32) {
        float xv = xr[j];
        p1 = fmaf(xv, a1[j], p1);
        p2 = fmaf(xv, a2[j], p2);
    }
#pragma unroll
    for (int o = 16; o; o >>= 1) {
        p1 += __shfl_xor_sync(0xffffffffu, p1, o);
        p2 += __shfl_xor_sync(0xffffffffu, p2, o);
    }
    if (lane == 0) { g_s1[n * 4 + h] = p1; g_s2[n * 4 + h] = p2; }
}

__global__ void hist_kernel(const void* __restrict__ edge) {
    int e = blockIdx.x * blockDim.x + threadIdx.x;
    if (e >= EE) return;
    int src = load_edge(edge, e);
    atomicAdd(&g_deg[src], 1);
}

// Single-block exclusive scan over 50000 degrees -> rowptr + cursor.
__global__ __launch_bounds__(256) void scan_kernel() {
    __shared__ int sums[256];
    const int t  = threadIdx.x;
    const int CH = (NN + 255) / 256;       // 196
    int beg = t * CH, end = min(beg + CH, NN);
    int s = 0;
    for (int i = beg; i < end; i++) s += g_deg[i];
    sums[t] = s;
    __syncthreads();
    if (t == 0) {
        int run = 0;
        for (int i = 0; i < 256; i++) { int v = sums[i]; sums[i] = run; run += v; }
    }
    __syncthreads();
    int run = sums[t];
    for (int i = beg; i < end; i++) {
        g_rowptr[i] = run;
        g_cursor[i] = run;
        run += g_deg[i];
    }
    if (t == 0) g_rowptr[NN] = EE;
}

// Per-edge: scores for 4 heads + scatter into CSR slots.
__global__ __launch_bounds__(256) void score_scatter_kernel(const void* __restrict__ edge) {
    int e = blockIdx.x * blockDim.x + threadIdx.x;
    if (e >= EE) return;
    int src = load_edge(edge, e);
    int dst = load_edge(edge, (long long)EE + e);
    float4 v1 = *reinterpret_cast<const float4*>(g_s1 + src * 4);
    float4 v2 = *reinterpret_cast<const float4*>(g_s2 + dst * 4);
    float4 sc;
    {
        float s0 = v1.x + v2.x, s1 = v1.y + v2.y, s2 = v1.z + v2.z, s3 = v1.w + v2.w;
        s0 = (s0 >= 0.f ? s0 : ALPHA_L * s0) * INV_SCALE;
        s1 = (s1 >= 0.f ? s1 : ALPHA_L * s1) * INV_SCALE;
        s2 = (s2 >= 0.f ? s2 : ALPHA_L * s2) * INV_SCALE;
        s3 = (s3 >= 0.f ? s3 : ALPHA_L * s3) * INV_SCALE;
        sc = make_float4(expf(s0), expf(s1), expf(s2), expf(s3));
    }
    int pos = atomicAdd(&g_cursor[src], 1);
    g_dsts[pos] = dst;
    g_es[pos]   = sc;
}

// One block (128 thr) per node: gather-aggregate + softmax denom + LayerNorm + ELU.
__global__ __launch_bounds__(128) void agg_ln_kernel(
    const float* __restrict__ gain, const float* __restrict__ beta,
    float* __restrict__ out)
{
    const int n = blockIdx.x;
    const int t = threadIdx.x;
    const int beg = g_rowptr[n], end = g_rowptr[n + 1];

    float a0 = 0.f, a1 = 0.f, a2 = 0.f, a3 = 0.f;
    float r0 = 0.f, r1 = 0.f, r2 = 0.f, r3 = 0.f;
    for (int i = beg; i < end; i++) {
        int d = g_dsts[i];
        float4 e = g_es[i];
        const float* xr = g_X + (size_t)d * COLS;
        a0 = fmaf(e.x, xr[t],            a0);
        a1 = fmaf(e.y, xr[HID + t],      a1);
        a2 = fmaf(e.z, xr[2 * HID + t],  a2);
        a3 = fmaf(e.w, xr[3 * HID + t],  a3);
        r0 += e.x; r1 += e.y; r2 += e.z; r3 += e.w;
    }
    float h0 = a0 / (r0 == 0.f ? 1.f : r0);
    float h1 = a1 / (r1 == 0.f ? 1.f : r1);
    float h2 = a2 / (r2 == 0.f ? 1.f : r2);
    float h3 = a3 / (r3 == 0.f ? 1.f : r3);

    float s  = h0 + h1 + h2 + h3;
    float ss = h0 * h0 + h1 * h1 + h2 * h2 + h3 * h3;
#pragma unroll
    for (int o = 16; o; o >>= 1) {
        s  += __shfl_xor_sync(0xffffffffu, s, o);
        ss += __shfl_xor_sync(0xffffffffu, ss, o);
    }
    __shared__ float rs[4], rss[4];
    int w = t >> 5;
    if ((t & 31) == 0) { rs[w] = s; rss[w] = ss; }
    __syncthreads();
    s  = rs[0] + rs[1] + rs[2] + rs[3];
    ss = rss[0] + rss[1] + rss[2] + rss[3];

    float mean = s * (1.f / 512.f);
    float var  = fmaxf((ss - 512.f * mean * mean) * (1.f / 511.f), 0.f);
    float inv  = 1.f / (sqrtf(var) + LN_EPS);

    float* orow = out + (size_t)n * COLS;
    float hv[4] = {h0, h1, h2, h3};
#pragma unroll
    for (int h = 0; h < 4; h++) {
        int c = h * HID + t;
        float v = gain[c] * (hv[h] - mean) * inv + beta[c];
        orow[c] = v > 0.f ? v : expm1f(v);
    }
}

// ---------------- launch -----------------------------------------------------
extern "C" void kernel_launch(void* const* d_in, const int* in_sizes, int n_in,
                              void* d_out, int out_size)
{
    (void)in_sizes; (void)n_in; (void)out_size;
    // metadata order: data, edge, embed_table, W, b, a_attn, ln_gain, ln_bias
    const void*  edge   = d_in[1];
    const float* emb    = (const float*)d_in[2];
    const float* W      = (const float*)d_in[3];
    const float* bias   = (const float*)d_in[4];
    const float* a_attn = (const float*)d_in[5];
    const float* gain   = (const float*)d_in[6];
    const float* beta   = (const float*)d_in[7];
    float* out = (float*)d_out;

    detect_kernel<<<1, 32>>>((const int*)edge);
    zero_deg_kernel<<<(NN + 255) / 256, 256>>>();

    dim3 gg((NN + 127) / 128, HEADS);
    gemm_kernel<<<gg, 256>>>(emb, W, bias);

    s_kernel<<<(NN * HEADS * 32 + 255) / 256, 256>>>(a_attn);

    hist_kernel<<<(EE + 255) / 256, 256>>>(edge);
    scan_kernel<<<1, 256>>>();
    score_scatter_kernel<<<(EE + 255) / 256, 256>>>(edge);

    agg_ln_kernel<<<NN, 128>>>(gain, beta, out);
}